// round 7
// baseline (speedup 1.0000x reference)
#include <cuda_runtime.h>

#define NW   10
#define QDIM 1024
#define NBLK 4
#define WPB  4                    // warps (batch elements) per CTA
#define NTHREADS (WPB * 32)

// Precomputed phase tables (params-only, batch-independent).
// B[k][s]  = exp(-i/2 * (p3.z[s] + p2.z[perm[s]]))       (applied with gather by perm)
// C'[k][s] = exp(-i/2 * (p5.z[perm[s]] + pA(k+1).z[s]))  (C of block k folded with A of block k+1)
// A[0] is a global phase on |0..0> -> dropped.
__device__ float2 gB[NBLK][QDIM];
__device__ float2 gC[NBLK][QDIM];
__device__ float2 gRy[NBLK][2][NW];   // (cos(th/2), sin(th/2))

// CX-ring permutation, closed form (GF(2)-linear):
// out_i = b_i ^ b_{i+1} (i=0..7), out8 = b8^b9^b0, out9 = b9^b0
__host__ __device__ __forceinline__ int perm_of(int s) {
    int lo = (s ^ (s >> 1)) & 0xFF;
    int b0 = s & 1, b8 = (s >> 8) & 1, b9 = (s >> 9) & 1;
    return lo | ((b8 ^ b9 ^ b0) << 8) | ((b9 ^ b0) << 9);
}

__device__ __forceinline__ float dotz(const float* __restrict__ p, int s) {
    float d = 0.f;
    #pragma unroll
    for (int w = 0; w < NW; ++w)
        d += ((s >> (9 - w)) & 1) ? -p[w] : p[w];
    return d;
}

__global__ __launch_bounds__(QDIM)
void precompute_kernel(const float* __restrict__ params) {
    int s = threadIdx.x;                          // 0..1023
    if (s < NBLK * 2 * NW) {                      // RY coefficient table
        int k = s / (2 * NW), r = s % (2 * NW);
        int sweep = r / NW, w = r % NW;
        float th = params[(k * 6 + (sweep ? 4 : 1)) * NW + w];
        gRy[k][sweep][w] = make_float2(cosf(0.5f * th), sinf(0.5f * th));
    }
    int ps = perm_of(s);
    #pragma unroll 1
    for (int k = 0; k < NBLK; ++k) {
        const float* p = params + k * 6 * NW;
        float aB = dotz(p + 3 * NW, s) + dotz(p + 2 * NW, ps);
        float aC = dotz(p + 5 * NW, ps);
        if (k < NBLK - 1)                         // fold A of block k+1 into C of block k
            aC += dotz(params + ((k + 1) * 6 + 0) * NW, s);
        float c, si;
        sincosf(-0.5f * aB, &si, &c); gB[k][s] = make_float2(c, si);
        sincosf(-0.5f * aC, &si, &c); gC[k][s] = make_float2(c, si);
    }
}

__device__ __forceinline__ float2 cmul(float2 a, float2 b) {
    return make_float2(a.x * b.x - a.y * b.y, a.x * b.y + a.y * b.x);
}
// RY 2x2 on a register pair: u' = c*u - s*v ; v' = s*u + c*v
__device__ __forceinline__ void rotp(float2& u, float2& v, float c, float s) {
    float2 nu = make_float2(fmaf(c, u.x, -s * v.x), fmaf(c, u.y, -s * v.y));
    float2 nv = make_float2(fmaf(s, u.x,  c * v.x), fmaf(s, u.y,  c * v.y));
    u = nu; v = nv;
}

// ---- building blocks (all force-inlined; r[] indices compile-time) ----
// RY on 5 wires living in register-index bits. base=4 -> wires 0..4 (L0),
// base=9 -> wires 5..9 (L1).
__device__ __forceinline__ void ry5(float2 r[32], const float2* __restrict__ ry, int base) {
    #pragma unroll
    for (int rb = 0; rb < 5; ++rb) {
        float2 rc = ry[base - rb];
        #pragma unroll
        for (int h = 0; h < 32; ++h)
            if (!(h & (1 << rb)))
                rotp(r[h], r[h | (1 << rb)], rc.x, rc.y);
    }
}
// transpose L0 -> L1 through the warp-private stage (swizzled)
__device__ __forceinline__ void transpose(float2 r[32], float2* st, int lane) {
    __syncwarp();
    #pragma unroll
    for (int h = 0; h < 32; ++h)
        st[(h << 5) | (lane ^ h)] = r[h];
    __syncwarp();
    #pragma unroll
    for (int h = 0; h < 32; ++h)
        r[h] = st[(lane << 5) | (h ^ lane)];
}
// write r (L1) -> gather by perm into L0, fused with diag table T
__device__ __forceinline__ void gatherT(float2 r[32], float2* st, int lane, int pladj,
                                        const float2* __restrict__ T) {
    __syncwarp();
    #pragma unroll
    for (int h = 0; h < 32; ++h)
        st[(lane << 5) | (h ^ lane)] = r[h];
    __syncwarp();
    #pragma unroll 8
    for (int h = 0; h < 32; ++h) {
        const int C = perm_of(h << 5);            // compile-time
        const int D = C ^ ((C >> 5) & 31);        // compile-time
        float2 v = st[D ^ pladj];
        r[h] = cmul(v, __ldg(&T[(h << 5) | lane]));
    }
}

// Layouts:
//   L0: amplitude s = (h<<5)|lane   (reg h = bits 9..5, lane = bits 4..0)
//   L1: amplitude s = (lane<<5)|h   (lane = bits 9..5, reg h = bits 4..0)
// Shared swizzle: phys(s) = s ^ ((s>>5)&31)  -> conflict-free for all 4 patterns.
__global__ __launch_bounds__(NTHREADS)
void qsim_kernel(const float* __restrict__ x, float* __restrict__ out) {
    __shared__ float2 stage[WPB][QDIM];

    const int lane = threadIdx.x & 31;
    const int wid  = threadIdx.x >> 5;
    const int b    = blockIdx.x * WPB + wid;
    float2* st = stage[wid];

    float xv[NW];
    #pragma unroll
    for (int w = 0; w < NW; ++w) xv[w] = __ldg(&x[b * NW + w]);

    // Per-thread gather constant: addr = D[h] ^ pladj
    const int pl    = perm_of(lane);
    const int pladj = pl ^ ((lane & 1) ? 0x18 : 0);

    // Encoding angle contribution from lane bits (wires 5..9)
    float langle = 0.f;
    #pragma unroll
    for (int w = 5; w < NW; ++w)
        langle += ((lane >> (9 - w)) & 1) ? -xv[w] : xv[w];

    float2 r[32];

    // ================= block 0 (peeled) =================
    // Sweep 1 on |0..0> yields a product state, built directly in L1.
    // L1: s = (lane<<5)|h.  wire w in [0,4] <-> lane bit (4-w);
    //                       wire w in [5,9] <-> h bit (9-w).
    {
        float pref = 1.f;
        #pragma unroll
        for (int w = 0; w < 5; ++w) {
            float2 rc = gRy[0][0][w];
            pref *= ((lane >> (4 - w)) & 1) ? rc.y : rc.x;
        }
        #pragma unroll
        for (int h = 0; h < 32; ++h) {
            float f = pref;
            #pragma unroll
            for (int w = 5; w < NW; ++w) {
                float2 rc = gRy[0][0][w];
                f *= ((h >> (9 - w)) & 1) ? rc.y : rc.x;
            }
            r[h] = make_float2(f, 0.f);
        }
    }
    gatherT(r, st, lane, pladj, gB[0]);
    ry5(r, gRy[0][1], 4);
    transpose(r, st, lane);
    ry5(r, gRy[0][1], 9);
    gatherT(r, st, lane, pladj, gC[0]);
    // encoding after block 0
    #pragma unroll 8
    for (int h = 0; h < 32; ++h) {
        float ang = langle;
        #pragma unroll
        for (int w = 0; w < 5; ++w)
            ang += ((h >> (4 - w)) & 1) ? -xv[w] : xv[w];
        float c, si;
        __sincosf(-0.5f * ang, &si, &c);
        r[h] = cmul(r[h], make_float2(c, si));
    }

    // ================= blocks 1..3 (uniform, branch-free body) =================
    #pragma unroll 1
    for (int k = 1; k < NBLK; ++k) {
        #pragma unroll
        for (int sweep = 0; sweep < 2; ++sweep) {
            ry5(r, gRy[k][sweep], 4);
            transpose(r, st, lane);
            ry5(r, gRy[k][sweep], 9);
            gatherT(r, st, lane, pladj, (sweep == 0) ? gB[k] : gC[k]);
        }
        if (k != NBLK - 1) {
            #pragma unroll 8
            for (int h = 0; h < 32; ++h) {
                float ang = langle;
                #pragma unroll
                for (int w = 0; w < 5; ++w)
                    ang += ((h >> (4 - w)) & 1) ? -xv[w] : xv[w];
                float c, si;
                __sincosf(-0.5f * ang, &si, &c);
                r[h] = cmul(r[h], make_float2(c, si));
            }
        }
    }

    // --- expectation values: out[b][w] = sum_s |a_s|^2 * z[w][s] ---
    float acc[NW];
    #pragma unroll
    for (int w = 0; w < NW; ++w) acc[w] = 0.f;
    float totP = 0.f;
    #pragma unroll
    for (int h = 0; h < 32; ++h) {
        float p = fmaf(r[h].x, r[h].x, r[h].y * r[h].y);
        totP += p;
        #pragma unroll
        for (int w = 0; w < 5; ++w)                     // wires 0..4 <- reg bits
            acc[w] += ((h >> (4 - w)) & 1) ? -p : p;
    }
    #pragma unroll
    for (int w = 5; w < NW; ++w)                        // wires 5..9 <- lane bits
        acc[w] = ((lane >> (9 - w)) & 1) ? -totP : totP;

    #pragma unroll
    for (int off = 16; off; off >>= 1)
        #pragma unroll
        for (int w = 0; w < NW; ++w)
            acc[w] += __shfl_xor_sync(0xffffffffu, acc[w], off);

    if (lane == 0) {
        #pragma unroll
        for (int w = 0; w < NW; ++w) out[b * NW + w] = acc[w];
    }
}

extern "C" void kernel_launch(void* const* d_in, const int* in_sizes, int n_in,
                              void* d_out, int out_size) {
    const float* x      = (const float*)d_in[0];
    const float* params = (const float*)d_in[1];
    float* out = (float*)d_out;
    int bsz = in_sizes[0] / NW;           // 2048
    precompute_kernel<<<1, QDIM>>>(params);
    qsim_kernel<<<bsz / WPB, NTHREADS>>>(x, out);
}

// round 8
// speedup vs baseline: 1.5311x; 1.5311x over previous
#include <cuda_runtime.h>

#define NW   10
#define QDIM 1024
#define NBLK 4
#define WPB  4                    // warps (batch elements) per CTA
#define NTHREADS (WPB * 32)

// Precomputed phase tables (params-only, batch-independent).
// B[k][s]  = exp(-i/2 * (p3.z[s] + p2.z[perm[s]]))       (applied with gather by perm)
// C'[k][s] = exp(-i/2 * (p5.z[perm[s]] + pA(k+1).z[s]))  (C of block k folded with A of block k+1)
// A[0] is a global phase on |0..0> -> dropped.
__device__ float2 gB[NBLK][QDIM];
__device__ float2 gC[NBLK][QDIM];
__device__ float2 gRy[NBLK][2][NW];   // (cos(th/2), sin(th/2))

// CX-ring permutation, closed form (GF(2)-linear):
// out_i = b_i ^ b_{i+1} (i=0..7), out8 = b8^b9^b0, out9 = b9^b0
__host__ __device__ __forceinline__ int perm_of(int s) {
    int lo = (s ^ (s >> 1)) & 0xFF;
    int b0 = s & 1, b8 = (s >> 8) & 1, b9 = (s >> 9) & 1;
    return lo | ((b8 ^ b9 ^ b0) << 8) | ((b9 ^ b0) << 9);
}

__device__ __forceinline__ float dotz(const float* __restrict__ p, int s) {
    float d = 0.f;
    #pragma unroll
    for (int w = 0; w < NW; ++w)
        d += ((s >> (9 - w)) & 1) ? -p[w] : p[w];
    return d;
}

__global__ __launch_bounds__(QDIM)
void precompute_kernel(const float* __restrict__ params) {
    int s = threadIdx.x;                          // 0..1023
    if (s < NBLK * 2 * NW) {                      // RY coefficient table
        int k = s / (2 * NW), r = s % (2 * NW);
        int sweep = r / NW, w = r % NW;
        float th = params[(k * 6 + (sweep ? 4 : 1)) * NW + w];
        gRy[k][sweep][w] = make_float2(cosf(0.5f * th), sinf(0.5f * th));
    }
    int ps = perm_of(s);
    #pragma unroll 1
    for (int k = 0; k < NBLK; ++k) {
        const float* p = params + k * 6 * NW;
        float aB = dotz(p + 3 * NW, s) + dotz(p + 2 * NW, ps);
        float aC = dotz(p + 5 * NW, ps);
        if (k < NBLK - 1)                         // fold A of block k+1 into C of block k
            aC += dotz(params + ((k + 1) * 6 + 0) * NW, s);
        float c, si;
        sincosf(-0.5f * aB, &si, &c); gB[k][s] = make_float2(c, si);
        sincosf(-0.5f * aC, &si, &c); gC[k][s] = make_float2(c, si);
    }
}

__device__ __forceinline__ float2 cmul(float2 a, float2 b) {
    return make_float2(a.x * b.x - a.y * b.y, a.x * b.y + a.y * b.x);
}
// RY 2x2 on a register pair: u' = c*u - s*v ; v' = s*u + c*v
__device__ __forceinline__ void rotp(float2& u, float2& v, float c, float s) {
    float2 nu = make_float2(fmaf(c, u.x, -s * v.x), fmaf(c, u.y, -s * v.y));
    float2 nv = make_float2(fmaf(s, u.x,  c * v.x), fmaf(s, u.y,  c * v.y));
    u = nu; v = nv;
}

// ---- building blocks (all force-inlined; r[] indices compile-time) ----
// RY on 5 wires living in register-index bits. base=4 -> wires 0..4 (L0),
// base=9 -> wires 5..9 (L1).
__device__ __forceinline__ void ry5(float2 r[32], const float2* __restrict__ ry, int base) {
    #pragma unroll
    for (int rb = 0; rb < 5; ++rb) {
        float2 rc = ry[base - rb];
        #pragma unroll
        for (int h = 0; h < 32; ++h)
            if (!(h & (1 << rb)))
                rotp(r[h], r[h | (1 << rb)], rc.x, rc.y);
    }
}
// transpose L0 -> L1 through the warp-private stage (swizzled)
__device__ __forceinline__ void transpose(float2 r[32], float2* st, int lane) {
    __syncwarp();
    #pragma unroll
    for (int h = 0; h < 32; ++h)
        st[(h << 5) | (lane ^ h)] = r[h];
    __syncwarp();
    #pragma unroll
    for (int h = 0; h < 32; ++h)
        r[h] = st[(lane << 5) | (h ^ lane)];
}
// write r (L1) -> gather by perm into L0, fused with diag table T
__device__ __forceinline__ void gatherT(float2 r[32], float2* st, int lane, int pladj,
                                        const float2* __restrict__ T) {
    __syncwarp();
    #pragma unroll
    for (int h = 0; h < 32; ++h)
        st[(lane << 5) | (h ^ lane)] = r[h];
    __syncwarp();
    #pragma unroll
    for (int h = 0; h < 32; ++h) {
        const int C = perm_of(h << 5);            // compile-time
        const int D = C ^ ((C >> 5) & 31);        // compile-time
        float2 v = st[D ^ pladj];
        r[h] = cmul(v, __ldg(&T[(h << 5) | lane]));
    }
}

// Layouts:
//   L0: amplitude s = (h<<5)|lane   (reg h = bits 9..5, lane = bits 4..0)
//   L1: amplitude s = (lane<<5)|h   (lane = bits 9..5, reg h = bits 4..0)
// Shared swizzle: phys(s) = s ^ ((s>>5)&31)  -> conflict-free for all 4 patterns.
__global__ __launch_bounds__(NTHREADS)
void qsim_kernel(const float* __restrict__ x, float* __restrict__ out) {
    __shared__ float2 stage[WPB][QDIM];

    const int lane = threadIdx.x & 31;
    const int wid  = threadIdx.x >> 5;
    const int b    = blockIdx.x * WPB + wid;
    float2* st = stage[wid];

    float xv[NW];
    #pragma unroll
    for (int w = 0; w < NW; ++w) xv[w] = __ldg(&x[b * NW + w]);

    // Per-thread gather constant: addr = D[h] ^ pladj
    const int pl    = perm_of(lane);
    const int pladj = pl ^ ((lane & 1) ? 0x18 : 0);

    // Encoding angle contribution from lane bits (wires 5..9)
    float langle = 0.f;
    #pragma unroll
    for (int w = 5; w < NW; ++w)
        langle += ((lane >> (9 - w)) & 1) ? -xv[w] : xv[w];

    float2 r[32];

    // ================= block 0 (peeled) =================
    // Sweep 1 on |0..0> yields a product state, built directly in L1.
    // L1: s = (lane<<5)|h.  wire w in [0,4] <-> lane bit (4-w);
    //                       wire w in [5,9] <-> h bit (9-w).
    {
        float pref = 1.f;
        #pragma unroll
        for (int w = 0; w < 5; ++w) {
            float2 rc = gRy[0][0][w];
            pref *= ((lane >> (4 - w)) & 1) ? rc.y : rc.x;
        }
        #pragma unroll
        for (int h = 0; h < 32; ++h) {
            float f = pref;
            #pragma unroll
            for (int w = 5; w < NW; ++w) {
                float2 rc = gRy[0][0][w];
                f *= ((h >> (9 - w)) & 1) ? rc.y : rc.x;
            }
            r[h] = make_float2(f, 0.f);
        }
    }
    gatherT(r, st, lane, pladj, gB[0]);
    ry5(r, gRy[0][1], 4);
    transpose(r, st, lane);
    ry5(r, gRy[0][1], 9);
    gatherT(r, st, lane, pladj, gC[0]);
    // encoding after block 0
    #pragma unroll
    for (int h = 0; h < 32; ++h) {
        float ang = langle;
        #pragma unroll
        for (int w = 0; w < 5; ++w)
            ang += ((h >> (4 - w)) & 1) ? -xv[w] : xv[w];
        float c, si;
        __sincosf(-0.5f * ang, &si, &c);
        r[h] = cmul(r[h], make_float2(c, si));
    }

    // ================= blocks 1..3 (FULLY UNROLLED: lets ptxas hoist/CSE
    // all shared-memory addresses and table offsets across the whole kernel,
    // which is what made the round-2 code shape fast) =================
    #pragma unroll
    for (int k = 1; k < NBLK; ++k) {
        #pragma unroll
        for (int sweep = 0; sweep < 2; ++sweep) {
            ry5(r, gRy[k][sweep], 4);
            transpose(r, st, lane);
            ry5(r, gRy[k][sweep], 9);
            gatherT(r, st, lane, pladj, (sweep == 0) ? gB[k] : gC[k]);
        }
        if (k != NBLK - 1) {
            #pragma unroll
            for (int h = 0; h < 32; ++h) {
                float ang = langle;
                #pragma unroll
                for (int w = 0; w < 5; ++w)
                    ang += ((h >> (4 - w)) & 1) ? -xv[w] : xv[w];
                float c, si;
                __sincosf(-0.5f * ang, &si, &c);
                r[h] = cmul(r[h], make_float2(c, si));
            }
        }
    }

    // --- expectation values: out[b][w] = sum_s |a_s|^2 * z[w][s] ---
    float acc[NW];
    #pragma unroll
    for (int w = 0; w < NW; ++w) acc[w] = 0.f;
    float totP = 0.f;
    #pragma unroll
    for (int h = 0; h < 32; ++h) {
        float p = fmaf(r[h].x, r[h].x, r[h].y * r[h].y);
        totP += p;
        #pragma unroll
        for (int w = 0; w < 5; ++w)                     // wires 0..4 <- reg bits
            acc[w] += ((h >> (4 - w)) & 1) ? -p : p;
    }
    #pragma unroll
    for (int w = 5; w < NW; ++w)                        // wires 5..9 <- lane bits
        acc[w] = ((lane >> (9 - w)) & 1) ? -totP : totP;

    #pragma unroll
    for (int off = 16; off; off >>= 1)
        #pragma unroll
        for (int w = 0; w < NW; ++w)
            acc[w] += __shfl_xor_sync(0xffffffffu, acc[w], off);

    if (lane == 0) {
        #pragma unroll
        for (int w = 0; w < NW; ++w) out[b * NW + w] = acc[w];
    }
}

extern "C" void kernel_launch(void* const* d_in, const int* in_sizes, int n_in,
                              void* d_out, int out_size) {
    const float* x      = (const float*)d_in[0];
    const float* params = (const float*)d_in[1];
    float* out = (float*)d_out;
    int bsz = in_sizes[0] / NW;           // 2048
    precompute_kernel<<<1, QDIM>>>(params);
    qsim_kernel<<<bsz / WPB, NTHREADS>>>(x, out);
}